// round 8
// baseline (speedup 1.0000x reference)
#include <cuda_runtime.h>
#include <cuda_fp16.h>
#include <cstdint>

#define BATCH 8
#define CIN   512
#define COUT  512
#define WDIM  512
#define HH    64
#define WW    64

#define PADW  66
#define NPIX  (PADW * PADW)    // 4356
#define KDIM  4608             // 9 taps * 512 ci
#define NKB   72               // K blocks of 64

// ---------------- device global scratch ------------------------------------
__device__ float  g_style[BATCH * CIN];
__device__ __half g_wA[(size_t)BATCH * COUT * KDIM];   // 36 MB
__device__ __half g_xt[(size_t)BATCH * NPIX * CIN];    // 34 MB

// ---------------- helpers ---------------------------------------------------
__device__ __forceinline__ uint32_t smem_u32(const void* p) {
    uint32_t a;
    asm("{ .reg .u64 t; cvta.to.shared.u64 t, %1; cvt.u32.u64 %0, t; }"
        : "=r"(a) : "l"(p));
    return a;
}
__device__ __forceinline__ void cp16(uint32_t dst, const void* src) {
    asm volatile("cp.async.cg.shared.global [%0], [%1], 16;" :: "r"(dst), "l"(src));
}
#define CP_COMMIT() asm volatile("cp.async.commit_group;" ::: "memory")
#define CP_WAIT1()  asm volatile("cp.async.wait_group 1;" ::: "memory")
#define CP_WAIT0()  asm volatile("cp.async.wait_group 0;" ::: "memory")

__device__ __forceinline__ void ldm4(uint32_t addr, uint32_t r[4]) {
    asm volatile("ldmatrix.sync.aligned.m8n8.x4.shared.b16 {%0,%1,%2,%3}, [%4];"
        : "=r"(r[0]), "=r"(r[1]), "=r"(r[2]), "=r"(r[3]) : "r"(addr));
}
__device__ __forceinline__ void mma_f16(float* d, const uint32_t* a,
                                        uint32_t b0, uint32_t b1) {
    asm volatile("mma.sync.aligned.m16n8k16.row.col.f32.f16.f16.f32 "
        "{%0,%1,%2,%3}, {%4,%5,%6,%7}, {%8,%9}, {%0,%1,%2,%3};"
        : "+f"(d[0]), "+f"(d[1]), "+f"(d[2]), "+f"(d[3])
        : "r"(a[0]), "r"(a[1]), "r"(a[2]), "r"(a[3]), "r"(b0), "r"(b1));
}

// ---------------------------------------------------------------------------
// Kernel A (launch #1): transpose x -> channel-last padded fp16,
// border zeroing fused (y==0 blocks clear the pad ring).
// ---------------------------------------------------------------------------
__global__ void xpose_kernel(const float* __restrict__ x) {
    __shared__ float tile[64][65];
    int cib = blockIdx.x, y = blockIdx.y, b = blockIdx.z;
    int ci0 = cib * 64, tid = threadIdx.x;
    const float* src = x + (((size_t)b * CIN + ci0) * HH + y) * WW;
#pragma unroll
    for (int i = 0; i < 16; i++) {
        int o = tid + i * 256;
        tile[o >> 6][o & 63] = src[(size_t)(o >> 6) * (HH * WW) + (o & 63)];
    }
    if (y == 0) {
        uint4 z = {0, 0, 0, 0};
        for (int o = tid; o < 260 * 8; o += 256) {
            int p = o >> 3, u = o & 7;
            int prow, pcol;
            if (p < 66)       { prow = 0;        pcol = p; }
            else if (p < 132) { prow = 65;       pcol = p - 66; }
            else if (p < 196) { prow = p - 131;  pcol = 0; }
            else              { prow = p - 195;  pcol = 65; }
            size_t idx = ((size_t)b * NPIX + (size_t)prow * PADW + pcol) * CIN
                       + ci0 + u * 8;
            *reinterpret_cast<uint4*>(g_xt + idx) = z;
        }
    }
    __syncthreads();
#pragma unroll
    for (int i = 0; i < 16; i++) {
        int o = tid + i * 256;
        int xc = o >> 6, ciL = o & 63;
        size_t oi = ((size_t)b * NPIX + (size_t)(y + 1) * PADW + (xc + 1)) * CIN
                  + ci0 + ciL;
        g_xt[oi] = __float2half_rn(tile[ciL][xc]);
    }
}

// ---------------------------------------------------------------------------
// Kernel B (launch #2): styles
// ---------------------------------------------------------------------------
__global__ void style_kernel(const float* __restrict__ w,
                             const float* __restrict__ aw,
                             const float* __restrict__ ab) {
    int warp = (blockIdx.x * blockDim.x + threadIdx.x) >> 5;
    int lane = threadIdx.x & 31;
    int b = warp >> 9, ci = warp & 511;
    const float* wr = w + (size_t)b * WDIM;
    const float* ar = aw + (size_t)ci * WDIM;
    float s = 0.f;
#pragma unroll
    for (int k = 0; k < WDIM / 32; k++)
        s += wr[lane + k * 32] * ar[lane + k * 32];
#pragma unroll
    for (int o = 16; o; o >>= 1) s += __shfl_xor_sync(~0u, s, o);
    if (lane == 0) g_style[b * CIN + ci] = s + ab[ci] + 1.0f;
}

// ---------------------------------------------------------------------------
// Kernel C (launch #3): modulate + demodulate -> A [b][co][tap*512+ci] fp16
// ---------------------------------------------------------------------------
__global__ void modw2_kernel(const float* __restrict__ weight) {
    __shared__ float ws[KDIM];
    __shared__ float red[8];
    int b = blockIdx.x >> 9, co = blockIdx.x & 511;
    int tid = threadIdx.x;
    const float* wb = weight + (size_t)co * KDIM;
#pragma unroll
    for (int i = 0; i < 18; i++) ws[tid + i * 256] = wb[tid + i * 256];
    __syncthreads();
    float v[18], ss = 0.f;
#pragma unroll
    for (int i = 0; i < 18; i++) {
        int o = tid + i * 256;
        int ci = o & 511, tap = o >> 9;
        float val = ws[ci * 9 + tap] * g_style[b * CIN + ci];
        v[i] = val;
        ss += val * val;
    }
#pragma unroll
    for (int o = 16; o; o >>= 1) ss += __shfl_xor_sync(~0u, ss, o);
    if ((tid & 31) == 0) red[tid >> 5] = ss;
    __syncthreads();
    float tot = 0.f;
#pragma unroll
    for (int i = 0; i < 8; i++) tot += red[i];
    float d = rsqrtf(tot + 1e-8f);
    size_t base = (size_t)blockIdx.x * KDIM;
#pragma unroll
    for (int i = 0; i < 18; i++) {
        int o = tid + i * 256;
        g_wA[base + o] = __float2half_rn(v[i] * d);
    }
}

// ---------------------------------------------------------------------------
// Kernel D (launch #4 == ncu capture slot): fp16 mma.sync implicit-GEMM conv
// CTA: 256 threads / 8 warps, warp grid 2x4, warp tile 64co x 64px.
// CTA tile 128co x 256px (4 output rows), K=4608 in 72 chunks of 64.
// Stage (48KB): A 16K | B 32K. 3 stages = 144KB -> 1 CTA/SM.
// smem reads/kb = 128KB vs 2048 MMA cycles -> port <= 69% (was 100% pinned).
// ---------------------------------------------------------------------------
#define STG 49152
#define SMEM_BYTES (3 * STG)

__device__ __forceinline__ void load_stage(int kb, uint32_t sbase, int b,
                                           int co0, int y0, int tid) {
    int tap = kb >> 3, cib = kb & 7;
    int dy = tap / 3 - 1, dx = tap % 3 - 1;
    // A: 128 rows x 8 16B-units = 1024 cp16 (4 per thread)
    const __half* A = g_wA + (size_t)(b * COUT + co0) * KDIM + kb * 64;
#pragma unroll
    for (int i = 0; i < 4; i++) {
        int o = tid + i * 256;
        int r = o >> 3, c = o & 7;
        uint32_t d = (uint32_t)(r * 128 + ((c ^ (r & 7)) << 4));
        cp16(sbase + d, A + (size_t)r * KDIM + c * 8);
    }
    // B: 256 pixel rows (4 y-rows x 64) x 8 units = 2048 cp16 (8 per thread)
    const __half* X = g_xt + (size_t)b * NPIX * CIN + cib * 64;
#pragma unroll
    for (int i = 0; i < 8; i++) {
        int o = tid + i * 256;
        int r = o >> 3, c = o & 7;
        int yl = r >> 6, xc = r & 63;
        int prow = (y0 + yl + dy + 1) * PADW + (xc + dx + 1);
        uint32_t d = (uint32_t)(r * 128 + ((c ^ (r & 7)) << 4));
        cp16(sbase + 16384 + d, X + (size_t)prow * CIN + c * 8);
    }
}

__global__ void __launch_bounds__(256)
conv_mma_kernel(const float* __restrict__ noise,
                const float* __restrict__ bias,
                float* __restrict__ out) {
    extern __shared__ __align__(1024) char smem[];
    uint32_t sb = smem_u32(smem);
    int tid = threadIdx.x, wid = tid >> 5, lane = tid & 31;
    int pxt = blockIdx.x, cot = blockIdx.y, b = blockIdx.z;
    int co0 = cot * 128, y0 = pxt * 4;
    int wm = wid >> 2, wn = wid & 3;          // warp grid 2 x 4

    float acc[4][8][4];
#pragma unroll
    for (int i = 0; i < 4; i++)
#pragma unroll
        for (int j = 0; j < 8; j++)
#pragma unroll
            for (int q = 0; q < 4; q++) acc[i][j][q] = 0.f;

    int a_row = wm * 64 + ((lane >> 3) & 1) * 8 + (lane & 7);
    int a_cc  = lane >> 4;
    int b_row = wn * 64 + ((lane >> 4) & 1) * 8 + (lane & 7);
    int b_cc  = (lane >> 3) & 1;

    load_stage(0, sb,       b, co0, y0, tid); CP_COMMIT();
    load_stage(1, sb + STG, b, co0, y0, tid); CP_COMMIT();

#pragma unroll 3
    for (int kb = 0; kb < NKB; kb++) {
        if (kb < NKB - 2) CP_WAIT1(); else CP_WAIT0();
        __syncthreads();
        if (kb + 2 < NKB) {
            load_stage(kb + 2, sb + ((kb + 2) % 3) * STG, b, co0, y0, tid);
            CP_COMMIT();
        }
        uint32_t sA = sb + (kb % 3) * STG;
        uint32_t sB = sA + 16384;
#pragma unroll
        for (int ks = 0; ks < 4; ks++) {
            uint32_t Ar[4][4], Br[4][4];
#pragma unroll
            for (int mf = 0; mf < 4; mf++) {
                int r = a_row + mf * 16;
                int cc = a_cc + ks * 2;
                ldm4(sA + r * 128 + ((cc ^ (r & 7)) << 4), Ar[mf]);
            }
#pragma unroll
            for (int g = 0; g < 4; g++) {
                int r = b_row + g * 16;
                int cc = b_cc + ks * 2;
                ldm4(sB + r * 128 + ((cc ^ (r & 7)) << 4), Br[g]);
            }
#pragma unroll
            for (int mf = 0; mf < 4; mf++)
#pragma unroll
                for (int nf = 0; nf < 8; nf++) {
                    int g = nf >> 1, h = (nf & 1) * 2;
                    mma_f16(acc[mf][nf], Ar[mf], Br[g][h], Br[g][h + 1]);
                }
        }
    }

    // ---- epilogue ----
    int g4 = lane >> 2, tg = lane & 3;
    float bv[4][2];
#pragma unroll
    for (int mf = 0; mf < 4; mf++) {
        bv[mf][0] = bias[co0 + wm * 64 + mf * 16 + g4];
        bv[mf][1] = bias[co0 + wm * 64 + mf * 16 + g4 + 8];
    }
#pragma unroll
    for (int mf = 0; mf < 4; mf++)
#pragma unroll
        for (int nf = 0; nf < 8; nf++) {
            int nl = wn * 64 + nf * 8 + tg * 2;          // 0..255
            int y = y0 + (nl >> 6), xx = nl & 63;
#pragma unroll
            for (int h = 0; h < 2; h++) {
                int co = co0 + wm * 64 + mf * 16 + g4 + h * 8;
                size_t oi = ((size_t)(b * COUT + co) * HH + y) * WW + xx;
                float2 nz = *reinterpret_cast<const float2*>(noise + oi);
                float vx = acc[mf][nf][h * 2 + 0] + nz.x + bv[mf][h];
                float vy = acc[mf][nf][h * 2 + 1] + nz.y + bv[mf][h];
                vx = (vx >= 0.f) ? vx : 0.2f * vx;
                vy = (vy >= 0.f) ? vy : 0.2f * vy;
                *reinterpret_cast<float2*>(out + oi) = make_float2(vx, vy);
            }
        }
}

// ---------------------------------------------------------------------------
// Launch. Inputs: 0:x 1:w 2:noise 3:weight 4:affine_w 5:affine_b 6:bias
// ---------------------------------------------------------------------------
extern "C" void kernel_launch(void* const* d_in, const int* in_sizes, int n_in,
                              void* d_out, int out_size) {
    const float* x        = (const float*)d_in[0];
    const float* w        = (const float*)d_in[1];
    const float* noise    = (const float*)d_in[2];
    const float* weight   = (const float*)d_in[3];
    const float* affine_w = (const float*)d_in[4];
    const float* affine_b = (const float*)d_in[5];
    const float* bias     = (const float*)d_in[6];
    float* out = (float*)d_out;

    cudaFuncSetAttribute(conv_mma_kernel,
                         cudaFuncAttributeMaxDynamicSharedMemorySize, SMEM_BYTES);

    xpose_kernel<<<dim3(8, 64, 8), 256>>>(x);
    style_kernel<<<512, 256>>>(w, affine_w, affine_b);
    modw2_kernel<<<BATCH * COUT, 256>>>(weight);
    conv_mma_kernel<<<dim3(16, 4, 8), 256, SMEM_BYTES>>>(noise, bias, out);
}

// round 9
// speedup vs baseline: 1.1738x; 1.1738x over previous
#include <cuda_runtime.h>
#include <cuda_fp16.h>
#include <cstdint>

#define BATCH 8
#define CIN   512
#define COUT  512
#define WDIM  512
#define HH    64
#define WW    64

#define PADW  66
#define NPIX  (PADW * PADW)    // 4356
#define KDIM  4608             // 9 taps * 512 ci
#define NITER 72               // 8 cib * 9 taps

// ---------------- device global scratch ------------------------------------
__device__ float  g_style[BATCH * CIN];
__device__ __half g_wA[(size_t)BATCH * COUT * KDIM];   // 36 MB
__device__ __half g_xt[(size_t)BATCH * NPIX * CIN];    // 34 MB

// ---------------- helpers ---------------------------------------------------
__device__ __forceinline__ uint32_t smem_u32(const void* p) {
    uint32_t a;
    asm("{ .reg .u64 t; cvta.to.shared.u64 t, %1; cvt.u32.u64 %0, t; }"
        : "=r"(a) : "l"(p));
    return a;
}
__device__ __forceinline__ void cp16(uint32_t dst, const void* src) {
    asm volatile("cp.async.cg.shared.global [%0], [%1], 16;" :: "r"(dst), "l"(src));
}
#define CP_COMMIT() asm volatile("cp.async.commit_group;" ::: "memory")
#define CP_WAIT0()  asm volatile("cp.async.wait_group 0;" ::: "memory")

__device__ __forceinline__ void ldm4(uint32_t addr, uint32_t r[4]) {
    asm volatile("ldmatrix.sync.aligned.m8n8.x4.shared.b16 {%0,%1,%2,%3}, [%4];"
        : "=r"(r[0]), "=r"(r[1]), "=r"(r[2]), "=r"(r[3]) : "r"(addr));
}
__device__ __forceinline__ void mma_f16(float* d, const uint32_t* a,
                                        uint32_t b0, uint32_t b1) {
    asm volatile("mma.sync.aligned.m16n8k16.row.col.f32.f16.f16.f32 "
        "{%0,%1,%2,%3}, {%4,%5,%6,%7}, {%8,%9}, {%0,%1,%2,%3};"
        : "+f"(d[0]), "+f"(d[1]), "+f"(d[2]), "+f"(d[3])
        : "r"(a[0]), "r"(a[1]), "r"(a[2]), "r"(a[3]), "r"(b0), "r"(b1));
}

// ---------------------------------------------------------------------------
// Kernel A (launch #1): transpose x -> channel-last padded fp16,
// border zeroing fused (y==0 blocks clear the pad ring).
// ---------------------------------------------------------------------------
__global__ void xpose_kernel(const float* __restrict__ x) {
    __shared__ float tile[64][65];
    int cib = blockIdx.x, y = blockIdx.y, b = blockIdx.z;
    int ci0 = cib * 64, tid = threadIdx.x;
    const float* src = x + (((size_t)b * CIN + ci0) * HH + y) * WW;
#pragma unroll
    for (int i = 0; i < 16; i++) {
        int o = tid + i * 256;
        tile[o >> 6][o & 63] = src[(size_t)(o >> 6) * (HH * WW) + (o & 63)];
    }
    if (y == 0) {
        uint4 z = {0, 0, 0, 0};
        for (int o = tid; o < 260 * 8; o += 256) {
            int p = o >> 3, u = o & 7;
            int prow, pcol;
            if (p < 66)       { prow = 0;        pcol = p; }
            else if (p < 132) { prow = 65;       pcol = p - 66; }
            else if (p < 196) { prow = p - 131;  pcol = 0; }
            else              { prow = p - 195;  pcol = 65; }
            size_t idx = ((size_t)b * NPIX + (size_t)prow * PADW + pcol) * CIN
                       + ci0 + u * 8;
            *reinterpret_cast<uint4*>(g_xt + idx) = z;
        }
    }
    __syncthreads();
#pragma unroll
    for (int i = 0; i < 16; i++) {
        int o = tid + i * 256;
        int xc = o >> 6, ciL = o & 63;
        size_t oi = ((size_t)b * NPIX + (size_t)(y + 1) * PADW + (xc + 1)) * CIN
                  + ci0 + ciL;
        g_xt[oi] = __float2half_rn(tile[ciL][xc]);
    }
}

// ---------------------------------------------------------------------------
// Kernel B (launch #2): styles
// ---------------------------------------------------------------------------
__global__ void style_kernel(const float* __restrict__ w,
                             const float* __restrict__ aw,
                             const float* __restrict__ ab) {
    int warp = (blockIdx.x * blockDim.x + threadIdx.x) >> 5;
    int lane = threadIdx.x & 31;
    int b = warp >> 9, ci = warp & 511;
    const float* wr = w + (size_t)b * WDIM;
    const float* ar = aw + (size_t)ci * WDIM;
    float s = 0.f;
#pragma unroll
    for (int k = 0; k < WDIM / 32; k++)
        s += wr[lane + k * 32] * ar[lane + k * 32];
#pragma unroll
    for (int o = 16; o; o >>= 1) s += __shfl_xor_sync(~0u, s, o);
    if (lane == 0) g_style[b * CIN + ci] = s + ab[ci] + 1.0f;
}

// ---------------------------------------------------------------------------
// Kernel C (launch #3): modulate + demodulate -> A [b][co][tap*512+ci] fp16
// ---------------------------------------------------------------------------
__global__ void modw2_kernel(const float* __restrict__ weight) {
    __shared__ float ws[KDIM];
    __shared__ float red[8];
    int b = blockIdx.x >> 9, co = blockIdx.x & 511;
    int tid = threadIdx.x;
    const float* wb = weight + (size_t)co * KDIM;
#pragma unroll
    for (int i = 0; i < 18; i++) ws[tid + i * 256] = wb[tid + i * 256];
    __syncthreads();
    float v[18], ss = 0.f;
#pragma unroll
    for (int i = 0; i < 18; i++) {
        int o = tid + i * 256;
        int ci = o & 511, tap = o >> 9;
        float val = ws[ci * 9 + tap] * g_style[b * CIN + ci];
        v[i] = val;
        ss += val * val;
    }
#pragma unroll
    for (int o = 16; o; o >>= 1) ss += __shfl_xor_sync(~0u, ss, o);
    if ((tid & 31) == 0) red[tid >> 5] = ss;
    __syncthreads();
    float tot = 0.f;
#pragma unroll
    for (int i = 0; i < 8; i++) tot += red[i];
    float d = rsqrtf(tot + 1e-8f);
    size_t base = (size_t)blockIdx.x * KDIM;
#pragma unroll
    for (int i = 0; i < 18; i++) {
        int o = tid + i * 256;
        g_wA[base + o] = __float2half_rn(v[i] * d);
    }
}

// ---------------------------------------------------------------------------
// Kernel D (launch #4 == ncu capture slot): fp16 mma.sync implicit-GEMM conv
// with X-patch reuse across taps.
// CTA: 256 thr / 8 warps, warp grid 2x4, warp tile 64co x 32px (R5 geometry).
// CTA tile 128co x 128px (2 output rows). K loop: cib-major (8) x tap (9).
// SMEM: A double buffer 2x16KB + patch double buffer 2x33KB = 98KB
//       -> 2 CTAs/SM, 16 warps/SM, regs capped at 128.
// Patch = 4 input rows x 66 cols x 64 ci, serves all 9 taps via per-lane
// ldmatrix row addressing p = (yl+dy+1)*66 + xc+dx+1.
// ---------------------------------------------------------------------------
#define OFF_P   32768
#define PATCH_B 33792                 // 264 rows * 128 B
#define SMEM_BYTES (OFF_P + 2 * PATCH_B)   // 100352

__device__ __forceinline__ void load_A(int u, uint32_t sbase, int b, int co0,
                                       int tid) {
    int cib = u / 9, tap = u - cib * 9;
    const __half* A = g_wA + (size_t)(b * COUT + co0) * KDIM + tap * 512 + cib * 64;
#pragma unroll
    for (int i = 0; i < 4; i++) {
        int o = tid + i * 256;
        int r = o >> 3, c = o & 7;
        cp16(sbase + r * 128 + ((c ^ (r & 7)) << 4), A + (size_t)r * KDIM + c * 8);
    }
}

__device__ __forceinline__ void load_patch(int cib, uint32_t sbase, int b,
                                           int y0, int tid) {
    const __half* X = g_xt + (size_t)b * NPIX * CIN + cib * 64;
#pragma unroll
    for (int i = 0; i < 9; i++) {
        int o = tid + i * 256;
        if (o < 264 * 8) {
            int p = o >> 3, c = o & 7;
            int qy = p / 66, col = p - qy * 66;
            cp16(sbase + p * 128 + ((c ^ (p & 7)) << 4),
                 X + ((size_t)(y0 + qy) * PADW + col) * CIN + c * 8);
        }
    }
}

__global__ void __launch_bounds__(256, 2)
conv_mma_kernel(const float* __restrict__ noise,
                const float* __restrict__ bias,
                float* __restrict__ out) {
    extern __shared__ __align__(1024) char smem[];
    uint32_t sb = smem_u32(smem);
    int tid = threadIdx.x, wid = tid >> 5, lane = tid & 31;
    int pxt = blockIdx.x, cot = blockIdx.y, b = blockIdx.z;
    int co0 = cot * 128, y0 = pxt * 2;
    int wm = wid >> 2, wn = wid & 3;          // warp grid 2 x 4

    float acc[4][4][4];
#pragma unroll
    for (int i = 0; i < 4; i++)
#pragma unroll
        for (int j = 0; j < 4; j++)
#pragma unroll
            for (int q = 0; q < 4; q++) acc[i][j][q] = 0.f;

    int a_row = wm * 64 + ((lane >> 3) & 1) * 8 + (lane & 7);
    int a_cc  = lane >> 4;
    int b_row = wn * 32 + ((lane >> 4) & 1) * 8 + (lane & 7);
    int b_cc  = (lane >> 3) & 1;

    // prologue: patch(cib0) then A(u=0)
    load_patch(0, sb + OFF_P, b, y0, tid); CP_COMMIT();
    load_A(0, sb, b, co0, tid);            CP_COMMIT();

    for (int cib = 0; cib < 8; cib++) {
        uint32_t sP = sb + OFF_P + (cib & 1) * PATCH_B;
#pragma unroll
        for (int tap = 0; tap < 9; tap++) {
            int u = cib * 9 + tap;
            int dy = tap / 3 - 1, dx = tap % 3 - 1;
            CP_WAIT0();
            __syncthreads();
            if (tap == 8 && cib < 7) {
                load_patch(cib + 1, sb + OFF_P + ((cib + 1) & 1) * PATCH_B,
                           b, y0, tid);
                CP_COMMIT();
            }
            if (u + 1 < NITER) {
                load_A(u + 1, sb + ((u + 1) & 1) * 16384, b, co0, tid);
                CP_COMMIT();
            }
            uint32_t sA = sb + (u & 1) * 16384;
            // per-tap patch row indices (hoisted out of ks loop)
            int n0 = b_row, n1 = b_row + 16;
            int p0 = ((n0 >> 6) + dy + 1) * 66 + (n0 & 63) + dx + 1;
            int p1 = ((n1 >> 6) + dy + 1) * 66 + (n1 & 63) + dx + 1;
#pragma unroll
            for (int ks = 0; ks < 4; ks++) {
                uint32_t Ar[4][4], Br[2][4];
#pragma unroll
                for (int mf = 0; mf < 4; mf++) {
                    int r = a_row + mf * 16;
                    int cc = a_cc + ks * 2;
                    ldm4(sA + r * 128 + ((cc ^ (r & 7)) << 4), Ar[mf]);
                }
                {
                    int cc = b_cc + ks * 2;
                    ldm4(sP + p0 * 128 + ((cc ^ (p0 & 7)) << 4), Br[0]);
                    ldm4(sP + p1 * 128 + ((cc ^ (p1 & 7)) << 4), Br[1]);
                }
#pragma unroll
                for (int mf = 0; mf < 4; mf++)
#pragma unroll
                    for (int nf = 0; nf < 4; nf++) {
                        int g = nf >> 1, h = (nf & 1) * 2;
                        mma_f16(acc[mf][nf], Ar[mf], Br[g][h], Br[g][h + 1]);
                    }
            }
        }
    }

    // ---- epilogue ----
    int g4 = lane >> 2, tg = lane & 3;
    float bv[4][2];
#pragma unroll
    for (int mf = 0; mf < 4; mf++) {
        bv[mf][0] = bias[co0 + wm * 64 + mf * 16 + g4];
        bv[mf][1] = bias[co0 + wm * 64 + mf * 16 + g4 + 8];
    }
#pragma unroll
    for (int mf = 0; mf < 4; mf++)
#pragma unroll
        for (int nf = 0; nf < 4; nf++) {
            int nl = wn * 32 + nf * 8 + tg * 2;
            int y = y0 + (nl >> 6), xx = nl & 63;
#pragma unroll
            for (int h = 0; h < 2; h++) {
                int co = co0 + wm * 64 + mf * 16 + g4 + h * 8;
                size_t oi = ((size_t)(b * COUT + co) * HH + y) * WW + xx;
                float2 nz = *reinterpret_cast<const float2*>(noise + oi);
                float vx = acc[mf][nf][h * 2 + 0] + nz.x + bv[mf][h];
                float vy = acc[mf][nf][h * 2 + 1] + nz.y + bv[mf][h];
                vx = (vx >= 0.f) ? vx : 0.2f * vx;
                vy = (vy >= 0.f) ? vy : 0.2f * vy;
                *reinterpret_cast<float2*>(out + oi) = make_float2(vx, vy);
            }
        }
}

// ---------------------------------------------------------------------------
// Launch. Inputs: 0:x 1:w 2:noise 3:weight 4:affine_w 5:affine_b 6:bias
// ---------------------------------------------------------------------------
extern "C" void kernel_launch(void* const* d_in, const int* in_sizes, int n_in,
                              void* d_out, int out_size) {
    const float* x        = (const float*)d_in[0];
    const float* w        = (const float*)d_in[1];
    const float* noise    = (const float*)d_in[2];
    const float* weight   = (const float*)d_in[3];
    const float* affine_w = (const float*)d_in[4];
    const float* affine_b = (const float*)d_in[5];
    const float* bias     = (const float*)d_in[6];
    float* out = (float*)d_out;

    cudaFuncSetAttribute(conv_mma_kernel,
                         cudaFuncAttributeMaxDynamicSharedMemorySize, SMEM_BYTES);

    xpose_kernel<<<dim3(8, 64, 8), 256>>>(x);
    style_kernel<<<512, 256>>>(w, affine_w, affine_b);
    modw2_kernel<<<BATCH * COUT, 256>>>(weight);
    conv_mma_kernel<<<dim3(32, 4, 8), 256, SMEM_BYTES>>>(noise, bias, out);
}

// round 10
// speedup vs baseline: 1.2255x; 1.0441x over previous
#include <cuda_runtime.h>
#include <cuda_fp16.h>
#include <cstdint>

#define BATCH 8
#define CIN   512
#define COUT  512
#define WDIM  512
#define HH    64
#define WW    64

#define PADW  66
#define NPIX  (PADW * PADW)    // 4356
#define KDIM  4608             // 9 taps * 512 ci

// ---------------- device global scratch ------------------------------------
__device__ float  g_style[BATCH * CIN];
__device__ __half g_wA[(size_t)BATCH * COUT * KDIM];   // 36 MB
__device__ __half g_xt[(size_t)BATCH * NPIX * CIN];    // 34 MB

// ---------------- helpers ---------------------------------------------------
__device__ __forceinline__ uint32_t smem_u32(const void* p) {
    uint32_t a;
    asm("{ .reg .u64 t; cvta.to.shared.u64 t, %1; cvt.u32.u64 %0, t; }"
        : "=r"(a) : "l"(p));
    return a;
}
__device__ __forceinline__ void cp16(uint32_t dst, const void* src) {
    asm volatile("cp.async.cg.shared.global [%0], [%1], 16;" :: "r"(dst), "l"(src));
}
#define CP_COMMIT() asm volatile("cp.async.commit_group;" ::: "memory")
#define CP_WAIT1()  asm volatile("cp.async.wait_group 1;" ::: "memory")
#define CP_WAIT0()  asm volatile("cp.async.wait_group 0;" ::: "memory")

__device__ __forceinline__ void ldm4(uint32_t addr, uint32_t r[4]) {
    asm volatile("ldmatrix.sync.aligned.m8n8.x4.shared.b16 {%0,%1,%2,%3}, [%4];"
        : "=r"(r[0]), "=r"(r[1]), "=r"(r[2]), "=r"(r[3]) : "r"(addr));
}
__device__ __forceinline__ void mma_f16(float* d, const uint32_t* a,
                                        uint32_t b0, uint32_t b1) {
    asm volatile("mma.sync.aligned.m16n8k16.row.col.f32.f16.f16.f32 "
        "{%0,%1,%2,%3}, {%4,%5,%6,%7}, {%8,%9}, {%0,%1,%2,%3};"
        : "+f"(d[0]), "+f"(d[1]), "+f"(d[2]), "+f"(d[3])
        : "r"(a[0]), "r"(a[1]), "r"(a[2]), "r"(a[3]), "r"(b0), "r"(b1));
}

// ---------------------------------------------------------------------------
// Kernel A (launch #1): transpose x -> channel-last padded fp16,
// border zeroing fused (y==0 blocks clear the pad ring).
// ---------------------------------------------------------------------------
__global__ void xpose_kernel(const float* __restrict__ x) {
    __shared__ float tile[64][65];
    int cib = blockIdx.x, y = blockIdx.y, b = blockIdx.z;
    int ci0 = cib * 64, tid = threadIdx.x;
    const float* src = x + (((size_t)b * CIN + ci0) * HH + y) * WW;
#pragma unroll
    for (int i = 0; i < 16; i++) {
        int o = tid + i * 256;
        tile[o >> 6][o & 63] = src[(size_t)(o >> 6) * (HH * WW) + (o & 63)];
    }
    if (y == 0) {
        uint4 z = {0, 0, 0, 0};
        for (int o = tid; o < 260 * 8; o += 256) {
            int p = o >> 3, u = o & 7;
            int prow, pcol;
            if (p < 66)       { prow = 0;        pcol = p; }
            else if (p < 132) { prow = 65;       pcol = p - 66; }
            else if (p < 196) { prow = p - 131;  pcol = 0; }
            else              { prow = p - 195;  pcol = 65; }
            size_t idx = ((size_t)b * NPIX + (size_t)prow * PADW + pcol) * CIN
                       + ci0 + u * 8;
            *reinterpret_cast<uint4*>(g_xt + idx) = z;
        }
    }
    __syncthreads();
#pragma unroll
    for (int i = 0; i < 16; i++) {
        int o = tid + i * 256;
        int xc = o >> 6, ciL = o & 63;
        size_t oi = ((size_t)b * NPIX + (size_t)(y + 1) * PADW + (xc + 1)) * CIN
                  + ci0 + ciL;
        g_xt[oi] = __float2half_rn(tile[ciL][xc]);
    }
}

// ---------------------------------------------------------------------------
// Kernel B (launch #2): styles
// ---------------------------------------------------------------------------
__global__ void style_kernel(const float* __restrict__ w,
                             const float* __restrict__ aw,
                             const float* __restrict__ ab) {
    int warp = (blockIdx.x * blockDim.x + threadIdx.x) >> 5;
    int lane = threadIdx.x & 31;
    int b = warp >> 9, ci = warp & 511;
    const float* wr = w + (size_t)b * WDIM;
    const float* ar = aw + (size_t)ci * WDIM;
    float s = 0.f;
#pragma unroll
    for (int k = 0; k < WDIM / 32; k++)
        s += wr[lane + k * 32] * ar[lane + k * 32];
#pragma unroll
    for (int o = 16; o; o >>= 1) s += __shfl_xor_sync(~0u, s, o);
    if (lane == 0) g_style[b * CIN + ci] = s + ab[ci] + 1.0f;
}

// ---------------------------------------------------------------------------
// Kernel C (launch #3): modulate + demodulate -> A [b][co][tap*512+ci] fp16
// ---------------------------------------------------------------------------
__global__ void modw2_kernel(const float* __restrict__ weight) {
    __shared__ float ws[KDIM];
    __shared__ float red[8];
    int b = blockIdx.x >> 9, co = blockIdx.x & 511;
    int tid = threadIdx.x;
    const float* wb = weight + (size_t)co * KDIM;
#pragma unroll
    for (int i = 0; i < 18; i++) ws[tid + i * 256] = wb[tid + i * 256];
    __syncthreads();
    float v[18], ss = 0.f;
#pragma unroll
    for (int i = 0; i < 18; i++) {
        int o = tid + i * 256;
        int ci = o & 511, tap = o >> 9;
        float val = ws[ci * 9 + tap] * g_style[b * CIN + ci];
        v[i] = val;
        ss += val * val;
    }
#pragma unroll
    for (int o = 16; o; o >>= 1) ss += __shfl_xor_sync(~0u, ss, o);
    if ((tid & 31) == 0) red[tid >> 5] = ss;
    __syncthreads();
    float tot = 0.f;
#pragma unroll
    for (int i = 0; i < 8; i++) tot += red[i];
    float d = rsqrtf(tot + 1e-8f);
    size_t base = (size_t)blockIdx.x * KDIM;
#pragma unroll
    for (int i = 0; i < 18; i++) {
        int o = tid + i * 256;
        g_wA[base + o] = __float2half_rn(v[i] * d);
    }
}

// ---------------------------------------------------------------------------
// Kernel D (launch #4 == ncu capture slot): fp16 mma.sync implicit-GEMM conv.
// CTA: 256 thr / 8 warps, warp grid 2x4, warp tile 64co x 32px.
// CTA tile 128co x 128px (2 output rows).
// K loop: cib (8) x tap-groups {0,1}{2,3}{4,5}{6,7}{8} -> 40 sync rounds.
// SMEM: A double buffer 2x32KB (2 taps/stage) + single 33KB X patch = 97KB
//       -> 2 CTAs/SM, 16 warps/SM, 128 regs.
// Patch (4 in-rows x 66 cols x 64 ci) reused by all 9 taps via per-lane
// ldmatrix row addressing; taps are compile-time in the unrolled group loop.
// ---------------------------------------------------------------------------
#define OFF_P   65536
#define PATCH_B 33792                 // 264 rows * 128 B
#define SMEM_BYTES (OFF_P + PATCH_B)  // 99328

__device__ __forceinline__ void load_patch(int cib, uint32_t sbase, int b,
                                           int y0, int tid) {
    const __half* X = g_xt + (size_t)b * NPIX * CIN + cib * 64;
#pragma unroll
    for (int i = 0; i < 9; i++) {
        int o = tid + i * 256;
        if (o < 264 * 8) {
            int p = o >> 3, c = o & 7;
            int qy = p / 66, col = p - qy * 66;
            cp16(sbase + p * 128 + ((c ^ (p & 7)) << 4),
                 X + ((size_t)(y0 + qy) * PADW + col) * CIN + c * 8);
        }
    }
}

__device__ __forceinline__ void load_Agrp(int cib, int g, uint32_t sbase,
                                          int b, int co0, int tid) {
    int nt = (g == 4) ? 1 : 2;
    for (int j = 0; j < nt; j++) {
        int tap = g * 2 + j;
        const __half* A = g_wA + (size_t)(b * COUT + co0) * KDIM
                        + tap * 512 + cib * 64;
#pragma unroll
        for (int i = 0; i < 4; i++) {
            int o = tid + i * 256;
            int r = o >> 3, c = o & 7;
            cp16(sbase + j * 16384 + r * 128 + ((c ^ (r & 7)) << 4),
                 A + (size_t)r * KDIM + c * 8);
        }
    }
}

__global__ void __launch_bounds__(256, 2)
conv_mma_kernel(const float* __restrict__ noise,
                const float* __restrict__ bias,
                float* __restrict__ out) {
    extern __shared__ __align__(1024) char smem[];
    uint32_t sb = smem_u32(smem);
    int tid = threadIdx.x, wid = tid >> 5, lane = tid & 31;
    int pxt = blockIdx.x, cot = blockIdx.y, b = blockIdx.z;
    int co0 = cot * 128, y0 = pxt * 2;
    int wm = wid >> 2, wn = wid & 3;          // warp grid 2 x 4

    float acc[4][4][4];
#pragma unroll
    for (int i = 0; i < 4; i++)
#pragma unroll
        for (int j = 0; j < 4; j++)
#pragma unroll
            for (int q = 0; q < 4; q++) acc[i][j][q] = 0.f;

    int a_row = wm * 64 + ((lane >> 3) & 1) * 8 + (lane & 7);
    int a_cc  = lane >> 4;
    int b_row = wn * 32 + ((lane >> 4) & 1) * 8 + (lane & 7);
    int b_cc  = (lane >> 3) & 1;
    uint32_t sP = sb + OFF_P;

    // prologue: patch(cib=0) then A group 0 of cib 0
    load_patch(0, sP, b, y0, tid); CP_COMMIT();
    load_Agrp(0, 0, sb, b, co0, tid); CP_COMMIT();

    for (int cib = 0; cib < 8; cib++) {
#pragma unroll
        for (int g = 0; g < 5; g++) {
            // ---- sync round: A(this group) ready, then prefetch next ----
            CP_WAIT0();
            __syncthreads();
            bool boundary = (g == 0) && (cib > 0);
            if (boundary) {                      // patch for this cib (exposed)
                load_patch(cib, sP, b, y0, tid);
                CP_COMMIT();
            }
            bool has_next = !(cib == 7 && g == 4);
            if (has_next) {
                int ncib = (g == 4) ? cib + 1 : cib;
                int ng   = (g == 4) ? 0 : g + 1;
                load_Agrp(ncib, ng, sb + (((cib + g + 1) & 1) << 15),
                          b, co0, tid);
                CP_COMMIT();
            }
            if (boundary) {                      // drain patch, keep A in flight
                if (has_next) CP_WAIT1(); else CP_WAIT0();
                __syncthreads();
            }
            uint32_t sA = sb + (((cib + g) & 1) << 15);

            // ---- compute 2 taps (1 for g==4), taps compile-time ----
#pragma unroll
            for (int j = 0; j < 2; j++) {
                if (g == 4 && j == 1) break;
                const int tap = g * 2 + j;
                const int dy = tap / 3 - 1, dx = tap % 3 - 1;
                int p0 = ((b_row >> 6) + dy + 1) * 66 + (b_row & 63) + dx + 1;
                int p1 = (((b_row + 16) >> 6) + dy + 1) * 66
                       + ((b_row + 16) & 63) + dx + 1;
                uint32_t sAt = sA + j * 16384;
#pragma unroll
                for (int ks = 0; ks < 4; ks++) {
                    uint32_t Ar[4][4], Br[2][4];
#pragma unroll
                    for (int mf = 0; mf < 4; mf++) {
                        int r = a_row + mf * 16;
                        int cc = a_cc + ks * 2;
                        ldm4(sAt + r * 128 + ((cc ^ (r & 7)) << 4), Ar[mf]);
                    }
                    {
                        int cc = b_cc + ks * 2;
                        ldm4(sP + p0 * 128 + ((cc ^ (p0 & 7)) << 4), Br[0]);
                        ldm4(sP + p1 * 128 + ((cc ^ (p1 & 7)) << 4), Br[1]);
                    }
#pragma unroll
                    for (int mf = 0; mf < 4; mf++)
#pragma unroll
                        for (int nf = 0; nf < 4; nf++) {
                            int gg = nf >> 1, h = (nf & 1) * 2;
                            mma_f16(acc[mf][nf], Ar[mf], Br[gg][h], Br[gg][h + 1]);
                        }
                }
            }
        }
    }

    // ---- epilogue ----
    int g4 = lane >> 2, tg = lane & 3;
    float bv[4][2];
#pragma unroll
    for (int mf = 0; mf < 4; mf++) {
        bv[mf][0] = bias[co0 + wm * 64 + mf * 16 + g4];
        bv[mf][1] = bias[co0 + wm * 64 + mf * 16 + g4 + 8];
    }
#pragma unroll
    for (int mf = 0; mf < 4; mf++)
#pragma unroll
        for (int nf = 0; nf < 4; nf++) {
            int nl = wn * 32 + nf * 8 + tg * 2;
            int y = y0 + (nl >> 6), xx = nl & 63;
#pragma unroll
            for (int h = 0; h < 2; h++) {
                int co = co0 + wm * 64 + mf * 16 + g4 + h * 8;
                size_t oi = ((size_t)(b * COUT + co) * HH + y) * WW + xx;
                float2 nz = *reinterpret_cast<const float2*>(noise + oi);
                float vx = acc[mf][nf][h * 2 + 0] + nz.x + bv[mf][h];
                float vy = acc[mf][nf][h * 2 + 1] + nz.y + bv[mf][h];
                vx = (vx >= 0.f) ? vx : 0.2f * vx;
                vy = (vy >= 0.f) ? vy : 0.2f * vy;
                *reinterpret_cast<float2*>(out + oi) = make_float2(vx, vy);
            }
        }
}

// ---------------------------------------------------------------------------
// Launch. Inputs: 0:x 1:w 2:noise 3:weight 4:affine_w 5:affine_b 6:bias
// ---------------------------------------------------------------------------
extern "C" void kernel_launch(void* const* d_in, const int* in_sizes, int n_in,
                              void* d_out, int out_size) {
    const float* x        = (const float*)d_in[0];
    const float* w        = (const float*)d_in[1];
    const float* noise    = (const float*)d_in[2];
    const float* weight   = (const float*)d_in[3];
    const float* affine_w = (const float*)d_in[4];
    const float* affine_b = (const float*)d_in[5];
    const float* bias     = (const float*)d_in[6];
    float* out = (float*)d_out;

    cudaFuncSetAttribute(conv_mma_kernel,
                         cudaFuncAttributeMaxDynamicSharedMemorySize, SMEM_BYTES);

    xpose_kernel<<<dim3(8, 64, 8), 256>>>(x);
    style_kernel<<<512, 256>>>(w, affine_w, affine_b);
    modw2_kernel<<<BATCH * COUT, 256>>>(weight);
    conv_mma_kernel<<<dim3(32, 4, 8), 256, SMEM_BYTES>>>(noise, bias, out);
}

// round 11
// speedup vs baseline: 1.2308x; 1.0043x over previous
#include <cuda_runtime.h>
#include <cuda_fp16.h>
#include <cstdint>

#define BATCH 8
#define CIN   512
#define COUT  512
#define WDIM  512
#define HH    64
#define WW    64

#define PADW  66
#define NPIX  (PADW * PADW)    // 4356
#define KDIM  4608             // 9 taps * 512 ci

// ---------------- device global scratch ------------------------------------
__device__ float  g_style[BATCH * CIN];
__device__ __half g_wA[(size_t)BATCH * COUT * KDIM];   // 36 MB
__device__ __half g_xt[(size_t)BATCH * NPIX * CIN];    // 34 MB

// ---------------- helpers ---------------------------------------------------
__device__ __forceinline__ uint32_t smem_u32(const void* p) {
    uint32_t a;
    asm("{ .reg .u64 t; cvta.to.shared.u64 t, %1; cvt.u32.u64 %0, t; }"
        : "=r"(a) : "l"(p));
    return a;
}
__device__ __forceinline__ void cp16(uint32_t dst, const void* src) {
    asm volatile("cp.async.cg.shared.global [%0], [%1], 16;" :: "r"(dst), "l"(src));
}
#define CP_COMMIT() asm volatile("cp.async.commit_group;" ::: "memory")
#define CP_WAIT1()  asm volatile("cp.async.wait_group 1;" ::: "memory")
#define CP_WAIT0()  asm volatile("cp.async.wait_group 0;" ::: "memory")

__device__ __forceinline__ void ldm4(uint32_t addr, uint32_t r[4]) {
    asm volatile("ldmatrix.sync.aligned.m8n8.x4.shared.b16 {%0,%1,%2,%3}, [%4];"
        : "=r"(r[0]), "=r"(r[1]), "=r"(r[2]), "=r"(r[3]) : "r"(addr));
}
__device__ __forceinline__ void mma_f16(float* d, const uint32_t* a,
                                        uint32_t b0, uint32_t b1) {
    asm volatile("mma.sync.aligned.m16n8k16.row.col.f32.f16.f16.f32 "
        "{%0,%1,%2,%3}, {%4,%5,%6,%7}, {%8,%9}, {%0,%1,%2,%3};"
        : "+f"(d[0]), "+f"(d[1]), "+f"(d[2]), "+f"(d[3])
        : "r"(a[0]), "r"(a[1]), "r"(a[2]), "r"(a[3]), "r"(b0), "r"(b1));
}

// ---------------------------------------------------------------------------
// Kernel A (launch #1): transpose x -> channel-last padded fp16,
// border zeroing fused (y==0 blocks clear the pad ring).
// ---------------------------------------------------------------------------
__global__ void xpose_kernel(const float* __restrict__ x) {
    __shared__ float tile[64][65];
    int cib = blockIdx.x, y = blockIdx.y, b = blockIdx.z;
    int ci0 = cib * 64, tid = threadIdx.x;
    const float* src = x + (((size_t)b * CIN + ci0) * HH + y) * WW;
#pragma unroll
    for (int i = 0; i < 16; i++) {
        int o = tid + i * 256;
        tile[o >> 6][o & 63] = src[(size_t)(o >> 6) * (HH * WW) + (o & 63)];
    }
    if (y == 0) {
        uint4 z = {0, 0, 0, 0};
        for (int o = tid; o < 260 * 8; o += 256) {
            int p = o >> 3, u = o & 7;
            int prow, pcol;
            if (p < 66)       { prow = 0;        pcol = p; }
            else if (p < 132) { prow = 65;       pcol = p - 66; }
            else if (p < 196) { prow = p - 131;  pcol = 0; }
            else              { prow = p - 195;  pcol = 65; }
            size_t idx = ((size_t)b * NPIX + (size_t)prow * PADW + pcol) * CIN
                       + ci0 + u * 8;
            *reinterpret_cast<uint4*>(g_xt + idx) = z;
        }
    }
    __syncthreads();
#pragma unroll
    for (int i = 0; i < 16; i++) {
        int o = tid + i * 256;
        int xc = o >> 6, ciL = o & 63;
        size_t oi = ((size_t)b * NPIX + (size_t)(y + 1) * PADW + (xc + 1)) * CIN
                  + ci0 + ciL;
        g_xt[oi] = __float2half_rn(tile[ciL][xc]);
    }
}

// ---------------------------------------------------------------------------
// Kernel B (launch #2): styles
// ---------------------------------------------------------------------------
__global__ void style_kernel(const float* __restrict__ w,
                             const float* __restrict__ aw,
                             const float* __restrict__ ab) {
    int warp = (blockIdx.x * blockDim.x + threadIdx.x) >> 5;
    int lane = threadIdx.x & 31;
    int b = warp >> 9, ci = warp & 511;
    const float* wr = w + (size_t)b * WDIM;
    const float* ar = aw + (size_t)ci * WDIM;
    float s = 0.f;
#pragma unroll
    for (int k = 0; k < WDIM / 32; k++)
        s += wr[lane + k * 32] * ar[lane + k * 32];
#pragma unroll
    for (int o = 16; o; o >>= 1) s += __shfl_xor_sync(~0u, s, o);
    if (lane == 0) g_style[b * CIN + ci] = s + ab[ci] + 1.0f;
}

// ---------------------------------------------------------------------------
// Kernel C (launch #3): modulate + demodulate, weight read ONCE per co.
// One block per co. sumsq(b) = sum_ci t9[ci] * s[b,ci]^2 with
// t9[ci] = sum_t w[co,ci,t]^2  (exact algebraic refactor of the per-b sum).
// ---------------------------------------------------------------------------
__global__ void modw2_kernel(const float* __restrict__ weight) {
    __shared__ float ws[KDIM];     // 18 KB
    __shared__ float t9[CIN];      // 2 KB
    __shared__ float sbv[CIN];     // 2 KB
    __shared__ float red[8];
    int co = blockIdx.x;
    int tid = threadIdx.x;
    const float* wb = weight + (size_t)co * KDIM;
#pragma unroll
    for (int i = 0; i < 18; i++) ws[tid + i * 256] = wb[tid + i * 256];
    __syncthreads();
#pragma unroll
    for (int i = 0; i < 2; i++) {
        int ci = tid + i * 256;
        float s = 0.f;
#pragma unroll
        for (int t = 0; t < 9; t++) { float v = ws[ci * 9 + t]; s += v * v; }
        t9[ci] = s;
    }
    __syncthreads();
    for (int b = 0; b < BATCH; b++) {
        float part = 0.f;
#pragma unroll
        for (int i = 0; i < 2; i++) {
            int ci = tid + i * 256;
            float s = g_style[b * CIN + ci];
            sbv[ci] = s;
            part += t9[ci] * s * s;
        }
#pragma unroll
        for (int o = 16; o; o >>= 1) part += __shfl_xor_sync(~0u, part, o);
        if ((tid & 31) == 0) red[tid >> 5] = part;
        __syncthreads();
        float tot = 0.f;
#pragma unroll
        for (int i = 0; i < 8; i++) tot += red[i];
        float d = rsqrtf(tot + 1e-8f);
        size_t base = ((size_t)b * COUT + co) * KDIM;
#pragma unroll
        for (int i = 0; i < 18; i++) {
            int o = tid + i * 256;
            int ci = o & 511, tap = o >> 9;      // note: sbv[ci]=thread's own writes
            g_wA[base + o] = __float2half_rn(ws[ci * 9 + tap] * sbv[ci] * d);
        }
        __syncthreads();
    }
}

// ---------------------------------------------------------------------------
// Kernel D (launch #4 == ncu capture slot): fp16 mma.sync implicit-GEMM conv.
// (unchanged from the 339.9us R9 version: 256 thr, 2x4 warps, 128co x 128px,
//  cib(8) x tap-groups {0,1}{2,3}{4,5}{6,7}{8} = 40 sync rounds, patch reuse,
//  A double buffer 2x32KB + single 33KB patch = 97KB, 2 CTAs/SM, 128 regs.)
// ---------------------------------------------------------------------------
#define OFF_P   65536
#define PATCH_B 33792                 // 264 rows * 128 B
#define SMEM_BYTES (OFF_P + PATCH_B)  // 99328

__device__ __forceinline__ void load_patch(int cib, uint32_t sbase, int b,
                                           int y0, int tid) {
    const __half* X = g_xt + (size_t)b * NPIX * CIN + cib * 64;
#pragma unroll
    for (int i = 0; i < 9; i++) {
        int o = tid + i * 256;
        if (o < 264 * 8) {
            int p = o >> 3, c = o & 7;
            int qy = p / 66, col = p - qy * 66;
            cp16(sbase + p * 128 + ((c ^ (p & 7)) << 4),
                 X + ((size_t)(y0 + qy) * PADW + col) * CIN + c * 8);
        }
    }
}

__device__ __forceinline__ void load_Agrp(int cib, int g, uint32_t sbase,
                                          int b, int co0, int tid) {
    int nt = (g == 4) ? 1 : 2;
    for (int j = 0; j < nt; j++) {
        int tap = g * 2 + j;
        const __half* A = g_wA + (size_t)(b * COUT + co0) * KDIM
                        + tap * 512 + cib * 64;
#pragma unroll
        for (int i = 0; i < 4; i++) {
            int o = tid + i * 256;
            int r = o >> 3, c = o & 7;
            cp16(sbase + j * 16384 + r * 128 + ((c ^ (r & 7)) << 4),
                 A + (size_t)r * KDIM + c * 8);
        }
    }
}

__global__ void __launch_bounds__(256, 2)
conv_mma_kernel(const float* __restrict__ noise,
                const float* __restrict__ bias,
                float* __restrict__ out) {
    extern __shared__ __align__(1024) char smem[];
    uint32_t sb = smem_u32(smem);
    int tid = threadIdx.x, wid = tid >> 5, lane = tid & 31;
    int pxt = blockIdx.x, cot = blockIdx.y, b = blockIdx.z;
    int co0 = cot * 128, y0 = pxt * 2;
    int wm = wid >> 2, wn = wid & 3;          // warp grid 2 x 4

    float acc[4][4][4];
#pragma unroll
    for (int i = 0; i < 4; i++)
#pragma unroll
        for (int j = 0; j < 4; j++)
#pragma unroll
            for (int q = 0; q < 4; q++) acc[i][j][q] = 0.f;

    int a_row = wm * 64 + ((lane >> 3) & 1) * 8 + (lane & 7);
    int a_cc  = lane >> 4;
    int b_row = wn * 32 + ((lane >> 4) & 1) * 8 + (lane & 7);
    int b_cc  = (lane >> 3) & 1;
    uint32_t sP = sb + OFF_P;

    load_patch(0, sP, b, y0, tid); CP_COMMIT();
    load_Agrp(0, 0, sb, b, co0, tid); CP_COMMIT();

    for (int cib = 0; cib < 8; cib++) {
#pragma unroll
        for (int g = 0; g < 5; g++) {
            CP_WAIT0();
            __syncthreads();
            bool boundary = (g == 0) && (cib > 0);
            if (boundary) {
                load_patch(cib, sP, b, y0, tid);
                CP_COMMIT();
            }
            bool has_next = !(cib == 7 && g == 4);
            if (has_next) {
                int ncib = (g == 4) ? cib + 1 : cib;
                int ng   = (g == 4) ? 0 : g + 1;
                load_Agrp(ncib, ng, sb + (((cib + g + 1) & 1) << 15),
                          b, co0, tid);
                CP_COMMIT();
            }
            if (boundary) {
                if (has_next) CP_WAIT1(); else CP_WAIT0();
                __syncthreads();
            }
            uint32_t sA = sb + (((cib + g) & 1) << 15);

#pragma unroll
            for (int j = 0; j < 2; j++) {
                if (g == 4 && j == 1) break;
                const int tap = g * 2 + j;
                const int dy = tap / 3 - 1, dx = tap % 3 - 1;
                int p0 = ((b_row >> 6) + dy + 1) * 66 + (b_row & 63) + dx + 1;
                int p1 = (((b_row + 16) >> 6) + dy + 1) * 66
                       + ((b_row + 16) & 63) + dx + 1;
                uint32_t sAt = sA + j * 16384;
#pragma unroll
                for (int ks = 0; ks < 4; ks++) {
                    uint32_t Ar[4][4], Br[2][4];
#pragma unroll
                    for (int mf = 0; mf < 4; mf++) {
                        int r = a_row + mf * 16;
                        int cc = a_cc + ks * 2;
                        ldm4(sAt + r * 128 + ((cc ^ (r & 7)) << 4), Ar[mf]);
                    }
                    {
                        int cc = b_cc + ks * 2;
                        ldm4(sP + p0 * 128 + ((cc ^ (p0 & 7)) << 4), Br[0]);
                        ldm4(sP + p1 * 128 + ((cc ^ (p1 & 7)) << 4), Br[1]);
                    }
#pragma unroll
                    for (int mf = 0; mf < 4; mf++)
#pragma unroll
                        for (int nf = 0; nf < 4; nf++) {
                            int gg = nf >> 1, h = (nf & 1) * 2;
                            mma_f16(acc[mf][nf], Ar[mf], Br[gg][h], Br[gg][h + 1]);
                        }
                }
            }
        }
    }

    // ---- epilogue ----
    int g4 = lane >> 2, tg = lane & 3;
    float bv[4][2];
#pragma unroll
    for (int mf = 0; mf < 4; mf++) {
        bv[mf][0] = bias[co0 + wm * 64 + mf * 16 + g4];
        bv[mf][1] = bias[co0 + wm * 64 + mf * 16 + g4 + 8];
    }
#pragma unroll
    for (int mf = 0; mf < 4; mf++)
#pragma unroll
        for (int nf = 0; nf < 4; nf++) {
            int nl = wn * 32 + nf * 8 + tg * 2;
            int y = y0 + (nl >> 6), xx = nl & 63;
#pragma unroll
            for (int h = 0; h < 2; h++) {
                int co = co0 + wm * 64 + mf * 16 + g4 + h * 8;
                size_t oi = ((size_t)(b * COUT + co) * HH + y) * WW + xx;
                float2 nz = *reinterpret_cast<const float2*>(noise + oi);
                float vx = acc[mf][nf][h * 2 + 0] + nz.x + bv[mf][h];
                float vy = acc[mf][nf][h * 2 + 1] + nz.y + bv[mf][h];
                vx = (vx >= 0.f) ? vx : 0.2f * vx;
                vy = (vy >= 0.f) ? vy : 0.2f * vy;
                *reinterpret_cast<float2*>(out + oi) = make_float2(vx, vy);
            }
        }
}

// ---------------------------------------------------------------------------
// Launch. Inputs: 0:x 1:w 2:noise 3:weight 4:affine_w 5:affine_b 6:bias
// ---------------------------------------------------------------------------
extern "C" void kernel_launch(void* const* d_in, const int* in_sizes, int n_in,
                              void* d_out, int out_size) {
    const float* x        = (const float*)d_in[0];
    const float* w        = (const float*)d_in[1];
    const float* noise    = (const float*)d_in[2];
    const float* weight   = (const float*)d_in[3];
    const float* affine_w = (const float*)d_in[4];
    const float* affine_b = (const float*)d_in[5];
    const float* bias     = (const float*)d_in[6];
    float* out = (float*)d_out;

    cudaFuncSetAttribute(conv_mma_kernel,
                         cudaFuncAttributeMaxDynamicSharedMemorySize, SMEM_BYTES);

    xpose_kernel<<<dim3(8, 64, 8), 256>>>(x);
    style_kernel<<<512, 256>>>(w, affine_w, affine_b);
    modw2_kernel<<<COUT, 256>>>(weight);
    conv_mma_kernel<<<dim3(32, 4, 8), 256, SMEM_BYTES>>>(noise, bias, out);
}